// round 1
// baseline (speedup 1.0000x reference)
#include <cuda_runtime.h>
#include <cstdint>

#define NG 4000      // genomes
#define NS 2048      // samples
#define NM 28000     // genes
#define NK 16000     // unique seqs

// Scratch (allocation-free: __device__ globals)
__device__ int g_count[NG];
__device__ int g_offset[NG + 1];
__device__ int g_genes[NM];

__device__ __forceinline__ float ex2f(float x) {
    float y;
    asm("ex2.approx.ftz.f32 %0, %1;" : "=f"(y) : "f"(x));
    return y;
}

__device__ __forceinline__ void red_add_v4(float* p, float4 v) {
    asm volatile("red.global.add.v4.f32 [%0], {%1, %2, %3, %4};"
                 :: "l"(p), "f"(v.x), "f"(v.y), "f"(v.z), "f"(v.w)
                 : "memory");
}

// ---------------- Pass 0: zero output + genome counters ----------------
__global__ void zero_kernel(float4* __restrict__ out4) {
    int i = blockIdx.x * blockDim.x + threadIdx.x;   // exactly NK*NS/4 threads
    out4[i] = make_float4(0.f, 0.f, 0.f, 0.f);
    if (i < NG) g_count[i] = 0;
}

// ---------------- Pass 1: histogram genes per genome ----------------
__global__ void hist_kernel(const int* __restrict__ genome_idx) {
    int g = blockIdx.x * blockDim.x + threadIdx.x;
    if (g < NM) atomicAdd(&g_count[genome_idx[g]], 1);
}

// ---------------- Pass 2: exclusive scan over 4000 counters (1 CTA) -------
__global__ void scan_kernel() {
    __shared__ int sh[1024];
    const int tid = threadIdx.x;
    const int base = tid * 4;
    int vals[4];
    int local = 0;
#pragma unroll
    for (int i = 0; i < 4; i++) {
        int v = (base + i < NG) ? g_count[base + i] : 0;
        vals[i] = local;            // exclusive within this thread
        local += v;
    }
    sh[tid] = local;
    __syncthreads();
    // inclusive Hillis-Steele scan over 1024 thread-sums
    for (int off = 1; off < 1024; off <<= 1) {
        int t = (tid >= off) ? sh[tid - off] : 0;
        __syncthreads();
        sh[tid] += t;
        __syncthreads();
    }
    int pre = (tid > 0) ? sh[tid - 1] : 0;
#pragma unroll
    for (int i = 0; i < 4; i++) {
        if (base + i < NG) {
            g_offset[base + i] = pre + vals[i];
            g_count[base + i] = 0;   // reuse as scatter cursor
        }
    }
    if (tid == 1023) g_offset[NG] = sh[1023];  // == NM
}

// ---------------- Pass 3: scatter gene ids into CSR ----------------
__global__ void scatter_kernel(const int* __restrict__ genome_idx) {
    int g = blockIdx.x * blockDim.x + threadIdx.x;
    if (g < NM) {
        int n = genome_idx[g];
        int p = atomicAdd(&g_count[n], 1);
        g_genes[g_offset[n] + p] = g;
    }
}

// ---------------- Pass 4: genome-major fused compute + vector-RED scatter --
// grid: (NG, NS/CHUNK), block: 256 threads, each thread owns 4 samples.
#define MAIN_THREADS 256
#define CHUNK (MAIN_THREADS * 4)   // 1024 samples per CTA
#define TILE 64                    // genes-per-genome tile (avg 7, max << 64)

__global__ void __launch_bounds__(MAIN_THREADS)
main_kernel(const float* __restrict__ A, const float* __restrict__ B,
            const float* __restrict__ bias, const float* __restrict__ pos,
            const int* __restrict__ seq_idx, float* __restrict__ out) {
    const int n  = blockIdx.x;                       // genome
    const int s0 = blockIdx.y * CHUNK + threadIdx.x * 4;

    const int beg = g_offset[n];
    const int end = g_offset[n + 1];
    const int cnt = end - beg;
    if (cnt == 0) return;                            // uniform per CTA

    const float4 a = *reinterpret_cast<const float4*>(A + (size_t)n * NS + s0);
    const float4 b = *reinterpret_cast<const float4*>(B + (size_t)n * NS + s0);

    __shared__ float s_pos[TILE];
    __shared__ float s_bias[TILE];
    __shared__ int   s_seq[TILE];

    for (int t0 = 0; t0 < cnt; t0 += TILE) {
        const int tc = min(TILE, cnt - t0);
        if (threadIdx.x < tc) {
            int g  = g_genes[beg + t0 + threadIdx.x];
            int sq = seq_idx[g];
            s_pos[threadIdx.x]  = pos[g];
            s_seq[threadIdx.x]  = sq;
            s_bias[threadIdx.x] = bias[sq];
        }
        __syncthreads();

        for (int j = 0; j < tc; j++) {
            const float p  = s_pos[j];
            const float wa = s_bias[j];
            const int   sq = s_seq[j];
            float4 v;
            v.x = wa * a.x * ex2f(fmaf(-p, b.x, 1.0f));
            v.y = wa * a.y * ex2f(fmaf(-p, b.y, 1.0f));
            v.z = wa * a.z * ex2f(fmaf(-p, b.z, 1.0f));
            v.w = wa * a.w * ex2f(fmaf(-p, b.w, 1.0f));
            red_add_v4(out + (size_t)sq * NS + s0, v);
        }
        __syncthreads();
    }
}

// ---------------- launch ----------------
extern "C" void kernel_launch(void* const* d_in, const int* in_sizes, int n_in,
                              void* d_out, int out_size) {
    const float* A          = (const float*)d_in[0];   // (4000, 2048)
    const float* B          = (const float*)d_in[1];   // (4000, 2048)
    const float* bias       = (const float*)d_in[2];   // (16000,)
    const float* pos        = (const float*)d_in[3];   // (28000,)
    const int*   genome_idx = (const int*)d_in[4];     // (28000,)
    const int*   seq_idx    = (const int*)d_in[5];     // (28000,)
    float*       out        = (float*)d_out;           // (16000, 2048)

    // Pass 0: zero 128MB output + counters. NK*NS/4 = 8,192,000 float4 stores.
    const int n4 = (NK * NS) / 4;
    zero_kernel<<<n4 / 256, 256>>>((float4*)out);

    // CSR build
    hist_kernel<<<(NM + 255) / 256, 256>>>(genome_idx);
    scan_kernel<<<1, 1024>>>();
    scatter_kernel<<<(NM + 255) / 256, 256>>>(genome_idx);

    // Main fused pass
    dim3 grid(NG, NS / CHUNK);
    main_kernel<<<grid, MAIN_THREADS>>>(A, B, bias, pos, seq_idx, out);
}